// round 1
// baseline (speedup 1.0000x reference)
#include <cuda_runtime.h>

#define NN   4
#define C    256
#define H    64
#define W    64
#define P    (H*W)
#define CCH  64
#define KK   5
#define K2   25
#define HO   128
#define WO   128
#define ENC  100

// scratch (device globals; no allocations allowed)
__device__ float g_comp[NN*CCH*P];      // 4 MB
__device__ float g_m[NN*ENC*P];         // 6.5 MB
__device__ float g_mask[NN*K2*HO*WO];   // 6.5 MB

// ---------------------------------------------------------------------------
// Kernel A: 1x1 conv channel compressor.  x(4,256,64,64) -> comp(4,64,64,64)
// block: 128 threads = 128 pixels, each thread holds 32 output-channel accs.
// grid: (32 pixel-blocks, 4 batch, 2 cc-halves)
// ---------------------------------------------------------------------------
__global__ void k_compress(const float* __restrict__ x,
                           const float* __restrict__ Wc,
                           const float* __restrict__ bc) {
    __shared__ float ws[32*64];
    const int n   = blockIdx.y;
    const int cc0 = blockIdx.z * 32;
    const int p   = blockIdx.x * 128 + threadIdx.x;

    float acc[32];
#pragma unroll
    for (int i = 0; i < 32; i++) acc[i] = 0.f;

    for (int c0 = 0; c0 < C; c0 += 64) {
        __syncthreads();
        for (int idx = threadIdx.x; idx < 32*64; idx += 128) {
            int i = idx >> 6, j = idx & 63;
            ws[idx] = Wc[(cc0 + i) * C + c0 + j];
        }
        __syncthreads();
#pragma unroll 4
        for (int c = 0; c < 64; c++) {
            float xv = x[(n*C + c0 + c)*P + p];
#pragma unroll
            for (int i = 0; i < 32; i++) acc[i] += ws[i*64 + c] * xv;
        }
    }
#pragma unroll
    for (int i = 0; i < 32; i++)
        g_comp[(n*CCH + cc0 + i)*P + p] = acc[i] + bc[cc0 + i];
}

// ---------------------------------------------------------------------------
// Kernel B: 3x3 conv encoder. comp(4,64,64,64) -> m(4,100,64,64), pad=1
// block: 256 threads = 16x16 pixel tile; 25 output channels per block (grid.z)
// channel dimension processed in chunks of 16 through shared memory.
// ---------------------------------------------------------------------------
__global__ void k_encode(const float* __restrict__ We,
                         const float* __restrict__ be) {
    __shared__ float tile[16*324];     // [c][18][18]
    __shared__ float wgt[25*16*9];     // [oc][c][3*3]
    const int tileid = blockIdx.x;     // 0..15
    const int h0 = (tileid >> 2) * 16;
    const int w0 = (tileid & 3) * 16;
    const int n  = blockIdx.y;
    const int oc0 = blockIdx.z * 25;
    const int tx = threadIdx.x & 15;
    const int ty = threadIdx.x >> 4;

    float acc[25];
#pragma unroll
    for (int i = 0; i < 25; i++) acc[i] = 0.f;

    for (int cs = 0; cs < CCH; cs += 16) {
        __syncthreads();
        for (int idx = threadIdx.x; idx < 16*324; idx += 256) {
            int c = idx / 324, r = idx % 324;
            int yy = r / 18, xx = r % 18;
            int gy = h0 + yy - 1, gx = w0 + xx - 1;
            float v = 0.f;
            if (gy >= 0 && gy < H && gx >= 0 && gx < W)
                v = g_comp[(n*CCH + cs + c)*P + gy*W + gx];
            tile[idx] = v;
        }
        for (int idx = threadIdx.x; idx < 25*16*9; idx += 256) {
            int oc = idx / 144, r = idx % 144;
            int c = r / 9, kk = r % 9;
            wgt[idx] = We[((oc0 + oc)*CCH + cs + c)*9 + kk];
        }
        __syncthreads();
        for (int c = 0; c < 16; c++) {
#pragma unroll
            for (int ky = 0; ky < 3; ky++) {
#pragma unroll
                for (int kx = 0; kx < 3; kx++) {
                    float v = tile[c*324 + (ty+ky)*18 + tx + kx];
                    int wb = c*9 + ky*3 + kx;
#pragma unroll
                    for (int oc = 0; oc < 25; oc++)
                        acc[oc] += wgt[oc*144 + wb] * v;
                }
            }
        }
    }
#pragma unroll
    for (int oc = 0; oc < 25; oc++)
        g_m[(n*ENC + oc0 + oc)*P + (h0+ty)*W + (w0+tx)] = acc[oc] + be[oc0 + oc];
}

// ---------------------------------------------------------------------------
// Kernel C: pixel-shuffle + softmax over 25.  m -> mask(4,25,128,128)
// one thread per output pixel.
// ---------------------------------------------------------------------------
__global__ void k_softmax() {
    int idx = blockIdx.x * 256 + threadIdx.x;   // 65536 total
    int n   = idx >> 14;
    int rem = idx & 16383;
    int ho = rem >> 7, wo = rem & 127;
    int h = ho >> 1, w = wo >> 1;
    int sub = ((ho & 1) << 1) + (wo & 1);
    float v[25];
    float mx = -1e30f;
#pragma unroll
    for (int k = 0; k < 25; k++) {
        v[k] = g_m[(n*ENC + k*4 + sub)*P + h*W + w];
        mx = fmaxf(mx, v[k]);
    }
    float s = 0.f;
#pragma unroll
    for (int k = 0; k < 25; k++) { v[k] = __expf(v[k] - mx); s += v[k]; }
    float inv = 1.f / s;
#pragma unroll
    for (int k = 0; k < 25; k++)
        g_mask[(n*K2 + k)*HO*WO + ho*WO + wo] = v[k]*inv;
}

// ---------------------------------------------------------------------------
// Kernel D: content-aware reassembly.
// out[n,c,2h+i,2w+j] = sum_k x_pad[n,c,h+ky-2,w+kx-2] * mask[n,k,2h+i,2w+j]
// block: 256 threads = 16x16 output tile (= 8x8 input tile); mask in regs,
// x tile (12x12, pad 2) in shared, channels looped in chunks of 32.
// ---------------------------------------------------------------------------
__global__ void k_reassemble(const float* __restrict__ x,
                             float* __restrict__ out) {
    __shared__ float xs[32*144];       // [c][12][12]
    const int t  = blockIdx.x;         // 0..63 tiles
    const int n  = blockIdx.y;
    const int h0 = (t >> 3) * 8, w0 = (t & 7) * 8;
    const int oy = threadIdx.x >> 4, ox = threadIdx.x & 15;
    const int ho = h0*2 + oy, wo = w0*2 + ox;
    const int h  = oy >> 1,  w  = ox >> 1;

    float mk[25];
#pragma unroll
    for (int k = 0; k < 25; k++)
        mk[k] = g_mask[(n*K2 + k)*HO*WO + ho*WO + wo];

    for (int cs = 0; cs < C; cs += 32) {
        __syncthreads();
        for (int idx = threadIdx.x; idx < 32*144; idx += 256) {
            int c = idx / 144, r = idx % 144;
            int yy = r / 12, xx = r % 12;
            int gy = h0 + yy - 2, gx = w0 + xx - 2;
            float v = 0.f;
            if (gy >= 0 && gy < H && gx >= 0 && gx < W)
                v = x[(n*C + cs + c)*P + gy*W + gx];
            xs[idx] = v;
        }
        __syncthreads();
        for (int c = 0; c < 32; c++) {
            float acc = 0.f;
#pragma unroll
            for (int ky = 0; ky < 5; ky++)
#pragma unroll
                for (int kx = 0; kx < 5; kx++)
                    acc += xs[c*144 + (h+ky)*12 + (w+kx)] * mk[ky*5 + kx];
            out[(n*C + cs + c)*HO*WO + ho*WO + wo] = acc;
        }
    }
}

// ---------------------------------------------------------------------------
extern "C" void kernel_launch(void* const* d_in, const int* in_sizes, int n_in,
                              void* d_out, int out_size) {
    const float* x  = (const float*)d_in[0];
    const float* Wc = (const float*)d_in[1];
    const float* bc = (const float*)d_in[2];
    const float* We = (const float*)d_in[3];
    const float* be = (const float*)d_in[4];
    float* out = (float*)d_out;

    k_compress  <<<dim3(32, NN, 2), 128>>>(x, Wc, bc);
    k_encode    <<<dim3(16, NN, 4), 256>>>(We, be);
    k_softmax   <<<256, 256>>>();
    k_reassemble<<<dim3(64, NN), 256>>>(x, out);
}

// round 2
// speedup vs baseline: 1.2905x; 1.2905x over previous
#include <cuda_runtime.h>

#define NN   4
#define C    256
#define H    64
#define W    64
#define P    (H*W)
#define CCH  64
#define K2   25
#define HO   128
#define WO   128
#define ENC  100

// scratch (device globals; no allocations allowed)
__device__ float g_comp[NN*CCH*P];   // 4 MB
__device__ float g_m[NN*ENC*P];      // 6.5 MB
__device__ float g_wt[C*CCH];        // 64 KB transposed compressor weights

// ---------------------------------------------------------------------------
// Kernel T: transpose Wc (64,256) -> g_wt (256,64)
// ---------------------------------------------------------------------------
__global__ void k_transpose(const float* __restrict__ Wc) {
    int idx = blockIdx.x * 256 + threadIdx.x;   // 16384
    int oc = idx & 63, c = idx >> 6;
    g_wt[c*CCH + oc] = Wc[oc*C + c];
}

// ---------------------------------------------------------------------------
// Kernel A: 1x1 conv channel compressor as 64x64 register-tiled GEMM.
// block = 256 threads, each computes 4 oc x 4 px. grid (64 px-tiles, 4 n).
// ---------------------------------------------------------------------------
__global__ __launch_bounds__(256)
void k_compress(const float* __restrict__ x, const float* __restrict__ bc) {
    __shared__ float Ws[16][64];
    __shared__ float Xs[16][64];
    const int n  = blockIdx.y;
    const int p0 = blockIdx.x * 64;
    const int tx = threadIdx.x & 15;   // px group
    const int ty = threadIdx.x >> 4;   // oc group

    float acc[4][4];
#pragma unroll
    for (int i = 0; i < 4; i++)
#pragma unroll
        for (int j = 0; j < 4; j++) acc[i][j] = 0.f;

    for (int c0 = 0; c0 < C; c0 += 16) {
        __syncthreads();
        for (int i = threadIdx.x; i < 1024; i += 256) {
            int k = i >> 6, oc = i & 63;
            Ws[k][oc] = g_wt[(c0 + k)*CCH + oc];
        }
        for (int i = threadIdx.x; i < 1024; i += 256) {
            int k = i >> 6, px = i & 63;
            Xs[k][px] = x[(n*C + c0 + k)*P + p0 + px];
        }
        __syncthreads();
#pragma unroll
        for (int k = 0; k < 16; k++) {
            float4 a = *(const float4*)&Ws[k][ty*4];
            float4 b = *(const float4*)&Xs[k][tx*4];
            float av[4] = {a.x, a.y, a.z, a.w};
            float bv[4] = {b.x, b.y, b.z, b.w};
#pragma unroll
            for (int i = 0; i < 4; i++)
#pragma unroll
                for (int j = 0; j < 4; j++) acc[i][j] += av[i]*bv[j];
        }
    }
#pragma unroll
    for (int i = 0; i < 4; i++) {
        int oc = ty*4 + i;
        float b = bc[oc];
        float4 o = {acc[i][0]+b, acc[i][1]+b, acc[i][2]+b, acc[i][3]+b};
        *(float4*)&g_comp[(n*CCH + oc)*P + p0 + tx*4] = o;
    }
}

// ---------------------------------------------------------------------------
// Kernel B: 3x3 conv encoder. comp(4,64,64,64) -> m(4,100,64,64), pad=1
// block = 128 threads = 8x16 pixel tile, 25 oc per block.
// weights staged as [c][tap][oc pad 28] -> broadcast LDS.128.
// grid (32 tiles, 4 n, 4 oc-groups) = 512 blocks.
// ---------------------------------------------------------------------------
__global__ __launch_bounds__(128)
void k_encode(const float* __restrict__ We, const float* __restrict__ be) {
    __shared__ float tile[16*180];     // [c][10][18]
    __shared__ float wgt[16*9*28];     // [c][tap][oc(25 pad 28)]
    const int t  = blockIdx.x;
    const int h0 = (t >> 2) * 8;
    const int w0 = (t & 3) * 16;
    const int n  = blockIdx.y;
    const int oc0 = blockIdx.z * 25;
    const int tx = threadIdx.x & 15;
    const int ty = threadIdx.x >> 4;   // 0..7

    float acc[25];
#pragma unroll
    for (int i = 0; i < 25; i++) acc[i] = 0.f;

    for (int cs = 0; cs < CCH; cs += 16) {
        __syncthreads();
        for (int idx = threadIdx.x; idx < 16*180; idx += 128) {
            int c = idx / 180, q = idx % 180;
            int yy = q / 18, xx = q % 18;
            int gy = h0 + yy - 1, gx = w0 + xx - 1;
            float v = 0.f;
            if (gy >= 0 && gy < H && gx >= 0 && gx < W)
                v = g_comp[(n*CCH + cs + c)*P + gy*W + gx];
            tile[idx] = v;
        }
        for (int idx = threadIdx.x; idx < 16*225; idx += 128) {
            int c = idx / 225, r = idx % 225;
            int tap = r / 25, oc = r % 25;
            wgt[(c*9 + tap)*28 + oc] = We[((oc0 + oc)*CCH + cs + c)*9 + tap];
        }
        __syncthreads();
#pragma unroll 1
        for (int c = 0; c < 16; c++) {
            float v[9];
#pragma unroll
            for (int ky = 0; ky < 3; ky++)
#pragma unroll
                for (int kx = 0; kx < 3; kx++)
                    v[ky*3+kx] = tile[c*180 + (ty+ky)*18 + tx + kx];
#pragma unroll
            for (int tap = 0; tap < 9; tap++) {
                const float* wp = &wgt[(c*9 + tap)*28];
                float vv = v[tap];
#pragma unroll
                for (int q = 0; q < 6; q++) {
                    float4 wv = *(const float4*)&wp[q*4];
                    acc[q*4+0] += vv*wv.x; acc[q*4+1] += vv*wv.y;
                    acc[q*4+2] += vv*wv.z; acc[q*4+3] += vv*wv.w;
                }
                acc[24] += vv*wp[24];
            }
        }
    }
#pragma unroll
    for (int oc = 0; oc < 25; oc++)
        g_m[(n*ENC + oc0 + oc)*P + (h0+ty)*W + (w0+tx)] = acc[oc] + be[oc0+oc];
}

// ---------------------------------------------------------------------------
// Kernel D: fused pixel-shuffle softmax + content-aware reassembly.
// block = 512 threads: pixel p(64 = 8x8 tile), i(2), cl(4 channel lanes).
// Each thread: 50 mask regs (j=0,1 x 25 taps), 2 channels/round, float2 stores.
// grid (64 tiles, 4 n).
// ---------------------------------------------------------------------------
__global__ __launch_bounds__(512)
void k_reassemble(const float* __restrict__ x, float* __restrict__ out) {
    __shared__ float ms[ENC*65];       // logits -> normalized masks [ch][px]
    __shared__ float xs[8*168];        // 8 channels, stride 168 (=8 mod 32)
    const int t  = blockIdx.x;
    const int n  = blockIdx.y;
    const int h0 = (t >> 3) * 8, w0 = (t & 7) * 8;
    const int cl = threadIdx.x & 3;
    const int i  = (threadIdx.x >> 2) & 1;
    const int p  = threadIdx.x >> 3;          // 0..63
    const int h  = p >> 3, w = p & 7;
    const int gh = h0 + h, gw = w0 + w;
    const int ho = 2*gh + i, wo = 2*gw;

    // stage encoder logits for this tile (coalesced)
    for (int idx = threadIdx.x; idx < ENC*64; idx += 512) {
        int ch = idx >> 6, pp = idx & 63;
        ms[ch*65 + pp] = g_m[(n*ENC + ch)*P + (h0 + (pp>>3))*W + w0 + (pp&7)];
    }
    __syncthreads();

    // softmax over 25 taps, each (p, sub) done by one thread (cl<2)
    if (cl < 2) {
        int sub = i*2 + cl;
        float tv[25], mx = -1e30f;
#pragma unroll
        for (int k = 0; k < 25; k++) {
            tv[k] = ms[(k*4 + sub)*65 + p];
            mx = fmaxf(mx, tv[k]);
        }
        float s = 0.f;
#pragma unroll
        for (int k = 0; k < 25; k++) { tv[k] = __expf(tv[k] - mx); s += tv[k]; }
        float inv = 1.f / s;
#pragma unroll
        for (int k = 0; k < 25; k++) ms[(k*4 + sub)*65 + p] = tv[k]*inv;
    }
    __syncthreads();

    // pull this thread's 50 mask weights (j=0,1) into registers
    float mk0[25], mk1[25];
#pragma unroll
    for (int k = 0; k < 25; k++) {
        mk0[k] = ms[(k*4 + i*2 + 0)*65 + p];
        mk1[k] = ms[(k*4 + i*2 + 1)*65 + p];
    }

    for (int r = 0; r < 32; r++) {     // 8 channels per round
        int c0 = r * 8;
        __syncthreads();
        for (int idx = threadIdx.x; idx < 8*144; idx += 512) {
            int c = idx / 144, q = idx % 144;
            int yy = q / 12, xx = q % 12;
            int gy = h0 + yy - 2, gx = w0 + xx - 2;
            float v = 0.f;
            if (gy >= 0 && gy < H && gx >= 0 && gx < W)
                v = x[(n*C + c0 + c)*P + gy*W + gx];
            xs[c*168 + yy*12 + xx] = v;
        }
        __syncthreads();
#pragma unroll
        for (int cc = 0; cc < 2; cc++) {
            int c = cl + cc*4;
            const float* xp = &xs[c*168 + h*12 + w];
            float a0 = 0.f, a1 = 0.f;
#pragma unroll
            for (int ky = 0; ky < 5; ky++)
#pragma unroll
                for (int kx = 0; kx < 5; kx++) {
                    float v = xp[ky*12 + kx];
                    int kk = ky*5 + kx;
                    a0 += v * mk0[kk];
                    a1 += v * mk1[kk];
                }
            float2 o = {a0, a1};
            *(float2*)&out[((n*C + c0 + c)*HO + ho)*WO + wo] = o;
        }
    }
}

// ---------------------------------------------------------------------------
extern "C" void kernel_launch(void* const* d_in, const int* in_sizes, int n_in,
                              void* d_out, int out_size) {
    const float* x  = (const float*)d_in[0];
    const float* Wc = (const float*)d_in[1];
    const float* bc = (const float*)d_in[2];
    const float* We = (const float*)d_in[3];
    const float* be = (const float*)d_in[4];
    float* out = (float*)d_out;

    k_transpose <<<64, 256>>>(Wc);
    k_compress  <<<dim3(64, NN), 256>>>(x, bc);
    k_encode    <<<dim3(32, NN, 4), 128>>>(We, be);
    k_reassemble<<<dim3(64, NN), 512>>>(x, out);
}

// round 3
// speedup vs baseline: 1.5074x; 1.1681x over previous
#include <cuda_runtime.h>

#define NN   4
#define C    256
#define H    64
#define W    64
#define P    (H*W)
#define CCH  64
#define K2   25
#define HO   128
#define WO   128
#define ENC  100

// scratch (device globals; no allocations allowed)
__device__ float g_comp[NN*CCH*P];   // 4 MB
__device__ float g_m[NN*ENC*P];      // 6.5 MB
__device__ float g_wt[C*CCH];        // 64 KB transposed compressor weights

// ---------------------------------------------------------------------------
// Kernel T: transpose Wc (64,256) -> g_wt (256,64)
// ---------------------------------------------------------------------------
__global__ void k_transpose(const float* __restrict__ Wc) {
    int idx = blockIdx.x * 256 + threadIdx.x;   // 16384
    int oc = idx & 63, c = idx >> 6;
    g_wt[c*CCH + oc] = Wc[oc*C + c];
}

// ---------------------------------------------------------------------------
// Kernel A: 1x1 conv channel compressor as 64oc x 32px register-tiled GEMM.
// block = 128 threads, each 4oc x 4px. grid (128 px-tiles, 4 n) = 512 blocks.
// ---------------------------------------------------------------------------
__global__ __launch_bounds__(128)
void k_compress(const float* __restrict__ x, const float* __restrict__ bc) {
    __shared__ float Ws[16][64];
    __shared__ float Xs[16][32];
    const int n  = blockIdx.y;
    const int p0 = blockIdx.x * 32;
    const int tx = threadIdx.x & 7;    // px group (4 px)
    const int ty = threadIdx.x >> 3;   // oc group (4 oc)

    float acc[4][4];
#pragma unroll
    for (int i = 0; i < 4; i++)
#pragma unroll
        for (int j = 0; j < 4; j++) acc[i][j] = 0.f;

    for (int c0 = 0; c0 < C; c0 += 16) {
        __syncthreads();
        for (int i = threadIdx.x; i < 1024; i += 128) {
            int k = i >> 6, oc = i & 63;
            Ws[k][oc] = g_wt[(c0 + k)*CCH + oc];
        }
        for (int i = threadIdx.x; i < 512; i += 128) {
            int k = i >> 5, px = i & 31;
            Xs[k][px] = x[(n*C + c0 + k)*P + p0 + px];
        }
        __syncthreads();
#pragma unroll
        for (int k = 0; k < 16; k++) {
            float4 a = *(const float4*)&Ws[k][ty*4];
            float4 b = *(const float4*)&Xs[k][tx*4];
            float av[4] = {a.x, a.y, a.z, a.w};
            float bv[4] = {b.x, b.y, b.z, b.w};
#pragma unroll
            for (int i = 0; i < 4; i++)
#pragma unroll
                for (int j = 0; j < 4; j++) acc[i][j] += av[i]*bv[j];
        }
    }
#pragma unroll
    for (int i = 0; i < 4; i++) {
        int oc = ty*4 + i;
        float b = bc[oc];
        float4 o = {acc[i][0]+b, acc[i][1]+b, acc[i][2]+b, acc[i][3]+b};
        *(float4*)&g_comp[(n*CCH + oc)*P + p0 + tx*4] = o;
    }
}

// ---------------------------------------------------------------------------
// Kernel B: 3x3 conv encoder. comp(4,64,64,64) -> m(4,100,64,64), pad=1
// block = 128 threads = 8x16 pixel tile, 25 oc per block.
// weights staged as [c][tap][oc pad 28] -> broadcast LDS.128.
// grid (32 tiles, 4 n, 4 oc-groups) = 512 blocks.
// ---------------------------------------------------------------------------
__global__ __launch_bounds__(128)
void k_encode(const float* __restrict__ We, const float* __restrict__ be) {
    __shared__ float tile[16*180];     // [c][10][18]
    __shared__ float wgt[16*9*28];     // [c][tap][oc(25 pad 28)]
    const int t  = blockIdx.x;
    const int h0 = (t >> 2) * 8;
    const int w0 = (t & 3) * 16;
    const int n  = blockIdx.y;
    const int oc0 = blockIdx.z * 25;
    const int tx = threadIdx.x & 15;
    const int ty = threadIdx.x >> 4;   // 0..7

    float acc[25];
#pragma unroll
    for (int i = 0; i < 25; i++) acc[i] = 0.f;

    for (int cs = 0; cs < CCH; cs += 16) {
        __syncthreads();
        for (int idx = threadIdx.x; idx < 16*180; idx += 128) {
            int c = idx / 180, q = idx % 180;
            int yy = q / 18, xx = q % 18;
            int gy = h0 + yy - 1, gx = w0 + xx - 1;
            float v = 0.f;
            if (gy >= 0 && gy < H && gx >= 0 && gx < W)
                v = g_comp[(n*CCH + cs + c)*P + gy*W + gx];
            tile[idx] = v;
        }
        for (int idx = threadIdx.x; idx < 16*225; idx += 128) {
            int c = idx / 225, r = idx % 225;
            int tap = r / 25, oc = r % 25;
            wgt[(c*9 + tap)*28 + oc] = We[((oc0 + oc)*CCH + cs + c)*9 + tap];
        }
        __syncthreads();
#pragma unroll 1
        for (int c = 0; c < 16; c++) {
            float v[9];
#pragma unroll
            for (int ky = 0; ky < 3; ky++)
#pragma unroll
                for (int kx = 0; kx < 3; kx++)
                    v[ky*3+kx] = tile[c*180 + (ty+ky)*18 + tx + kx];
#pragma unroll
            for (int tap = 0; tap < 9; tap++) {
                const float* wp = &wgt[(c*9 + tap)*28];
                float vv = v[tap];
#pragma unroll
                for (int q = 0; q < 6; q++) {
                    float4 wv = *(const float4*)&wp[q*4];
                    acc[q*4+0] += vv*wv.x; acc[q*4+1] += vv*wv.y;
                    acc[q*4+2] += vv*wv.z; acc[q*4+3] += vv*wv.w;
                }
                acc[24] += vv*wp[24];
            }
        }
    }
#pragma unroll
    for (int oc = 0; oc < 25; oc++)
        g_m[(n*ENC + oc0 + oc)*P + (h0+ty)*W + (w0+tx)] = acc[oc] + be[oc0+oc];
}

// ---------------------------------------------------------------------------
// Kernel D: fused pixel-shuffle softmax + content-aware reassembly.
// block = 256 threads = pixel p(64 = 8x8 tile) x cl(4 channel lanes).
// Each thread: ALL 4 subpixel mask sets in regs (100) -> 1 LDS : 4 FMA.
// 64 channels per block (grid.z = 4), 4 rounds of 16 channels.
// Staging addresses precomputed once (no per-round div/mod).
// grid (64 tiles, 4 n, 4 cgrp) = 1024 blocks.
// ---------------------------------------------------------------------------
__global__ __launch_bounds__(256, 2)
void k_reassemble(const float* __restrict__ x, float* __restrict__ out) {
    __shared__ float ms[ENC*65];       // logits -> normalized masks [ch][px]
    __shared__ float xs[16*168];       // 16 channels, stride 168 (=8 mod 32)
    const int t   = blockIdx.x;
    const int n   = blockIdx.y;
    const int c00 = blockIdx.z * 64;
    const int h0 = (t >> 3) * 8, w0 = (t & 7) * 8;
    const int cl = threadIdx.x & 3;
    const int p  = threadIdx.x >> 2;          // 0..63
    const int h  = p >> 3, w = p & 7;
    const int gh = h0 + h, gw = w0 + w;

    // stage encoder logits for this tile (coalesced)
    for (int idx = threadIdx.x; idx < ENC*64; idx += 256) {
        int ch = idx >> 6, pp = idx & 63;
        ms[ch*65 + pp] = g_m[(n*ENC + ch)*P + (h0 + (pp>>3))*W + w0 + (pp&7)];
    }
    __syncthreads();

    // softmax over 25 taps: thread -> (pixel p, sub = cl); all 256 busy
    {
        float tv[25], mx = -1e30f;
#pragma unroll
        for (int k = 0; k < 25; k++) {
            tv[k] = ms[(k*4 + cl)*65 + p];
            mx = fmaxf(mx, tv[k]);
        }
        float s = 0.f;
#pragma unroll
        for (int k = 0; k < 25; k++) { tv[k] = __expf(tv[k] - mx); s += tv[k]; }
        float inv = 1.f / s;
#pragma unroll
        for (int k = 0; k < 25; k++) ms[(k*4 + cl)*65 + p] = tv[k]*inv;
    }
    __syncthreads();

    // all 4 subpixel mask sets into registers (broadcast LDS over cl)
    float mk0[25], mk1[25], mk2[25], mk3[25];
#pragma unroll
    for (int k = 0; k < 25; k++) {
        mk0[k] = ms[(k*4 + 0)*65 + p];
        mk1[k] = ms[(k*4 + 1)*65 + p];
        mk2[k] = ms[(k*4 + 2)*65 + p];
        mk3[k] = ms[(k*4 + 3)*65 + p];
    }

    // precompute staging source offset once (thread < 144 owns one slot)
    int sp = -1;
    if (threadIdx.x < 144) {
        int yy = threadIdx.x / 12, xx = threadIdx.x % 12;
        int gy = h0 + yy - 2, gx = w0 + xx - 2;
        if (gy >= 0 && gy < H && gx >= 0 && gx < W) sp = gy*W + gx;
    }
    const float* xb = x + (n*C + c00)*P;
    float* ob = out + (size_t)(n*C + c00)*HO*WO + (2*gh)*WO + 2*gw;

    for (int rr = 0; rr < 4; rr++) {
        __syncthreads();
        if (threadIdx.x < 144) {
            const float* xc = xb + rr*16*P;
#pragma unroll
            for (int c = 0; c < 16; c++)
                xs[c*168 + threadIdx.x] = (sp >= 0) ? xc[c*P + sp] : 0.f;
        }
        __syncthreads();
#pragma unroll
        for (int cc = 0; cc < 4; cc++) {
            int c = cl + cc*4;                 // bank = 8*cl + w: conflict-free
            const float* xp = &xs[c*168 + h*12 + w];
            float a0 = 0.f, a1 = 0.f, a2 = 0.f, a3 = 0.f;
#pragma unroll
            for (int ky = 0; ky < 5; ky++)
#pragma unroll
                for (int kx = 0; kx < 5; kx++) {
                    float v = xp[ky*12 + kx];
                    int k = ky*5 + kx;
                    a0 += v*mk0[k]; a1 += v*mk1[k];
                    a2 += v*mk2[k]; a3 += v*mk3[k];
                }
            float* o = ob + (size_t)(rr*16 + c)*HO*WO;
            *(float2*)o        = make_float2(a0, a1);
            *(float2*)(o + WO) = make_float2(a2, a3);
        }
    }
}

// ---------------------------------------------------------------------------
extern "C" void kernel_launch(void* const* d_in, const int* in_sizes, int n_in,
                              void* d_out, int out_size) {
    const float* x  = (const float*)d_in[0];
    const float* Wc = (const float*)d_in[1];
    const float* bc = (const float*)d_in[2];
    const float* We = (const float*)d_in[3];
    const float* be = (const float*)d_in[4];
    float* out = (float*)d_out;

    k_transpose <<<64, 256>>>(Wc);
    k_compress  <<<dim3(128, NN), 128>>>(x, bc);
    k_encode    <<<dim3(32, NN, 4), 128>>>(We, be);
    k_reassemble<<<dim3(64, NN, 4), 256>>>(x, out);
}

// round 4
// speedup vs baseline: 1.7873x; 1.1856x over previous
#include <cuda_runtime.h>

#define NN   4
#define C    256
#define H    64
#define W    64
#define P    (H*W)
#define CCH  64
#define K2   25
#define HO   128
#define WO   128
#define ENC  100

typedef unsigned long long u64;

__device__ __forceinline__ u64 pack2(float lo, float hi) {
    u64 r; asm("mov.b64 %0, {%1,%2};" : "=l"(r) : "f"(lo), "f"(hi)); return r;
}
__device__ __forceinline__ u64 dup2(float v) {
    u64 r; asm("mov.b64 %0, {%1,%1};" : "=l"(r) : "f"(v)); return r;
}
__device__ __forceinline__ void unpack2(u64 v, float& lo, float& hi) {
    asm("mov.b64 {%0,%1}, %2;" : "=f"(lo), "=f"(hi) : "l"(v));
}
__device__ __forceinline__ u64 fma2(u64 a, u64 b, u64 c) {
    u64 d; asm("fma.rn.f32x2 %0, %1, %2, %3;" : "=l"(d) : "l"(a), "l"(b), "l"(c)); return d;
}
__device__ __forceinline__ u64 add2(u64 a, u64 b) {
    u64 d; asm("add.rn.f32x2 %0, %1, %2;" : "=l"(d) : "l"(a), "l"(b)); return d;
}

// scratch (device globals; no allocations allowed)
__device__ float g_comp[NN*CCH*P];   // 4 MB
__device__ float g_m[NN*ENC*P];      // 6.5 MB  (K-half 0)
__device__ float g_m2[NN*ENC*P];     // 6.5 MB  (K-half 1)
__device__ float g_wt[C*CCH];        // transposed compressor weights

// ---------------------------------------------------------------------------
// Kernel T: transpose Wc (64,256) -> g_wt (256,64)
// ---------------------------------------------------------------------------
__global__ void k_transpose(const float* __restrict__ Wc) {
    int idx = blockIdx.x * 256 + threadIdx.x;
    int oc = idx & 63, c = idx >> 6;
    g_wt[c*CCH + oc] = Wc[oc*C + c];
}

// ---------------------------------------------------------------------------
// Kernel A: 1x1 conv compressor, 64oc x 32px tiles, packed f32x2 over px.
// ---------------------------------------------------------------------------
__global__ __launch_bounds__(128)
void k_compress(const float* __restrict__ x, const float* __restrict__ bc) {
    __shared__ __align__(16) float Ws[16][64];
    __shared__ __align__(16) float Xs[16][32];
    const int n  = blockIdx.y;
    const int p0 = blockIdx.x * 32;
    const int tx = threadIdx.x & 7;    // px group (4 px = 2 pairs)
    const int ty = threadIdx.x >> 3;   // oc group (4 oc)

    u64 acc[4][2];
#pragma unroll
    for (int i = 0; i < 4; i++) { acc[i][0] = 0ull; acc[i][1] = 0ull; }

    for (int c0 = 0; c0 < C; c0 += 16) {
        __syncthreads();
        for (int i = threadIdx.x; i < 1024; i += 128) {
            int k = i >> 6, oc = i & 63;
            Ws[k][oc] = g_wt[(c0 + k)*CCH + oc];
        }
        for (int i = threadIdx.x; i < 512; i += 128) {
            int k = i >> 5, px = i & 31;
            Xs[k][px] = x[(n*C + c0 + k)*P + p0 + px];
        }
        __syncthreads();
#pragma unroll
        for (int k = 0; k < 16; k++) {
            float4 a = *(const float4*)&Ws[k][ty*4];
            u64 b01 = *(const u64*)&Xs[k][tx*4];
            u64 b23 = *(const u64*)&Xs[k][tx*4 + 2];
            float av[4] = {a.x, a.y, a.z, a.w};
#pragma unroll
            for (int i = 0; i < 4; i++) {
                u64 d = dup2(av[i]);
                acc[i][0] = fma2(d, b01, acc[i][0]);
                acc[i][1] = fma2(d, b23, acc[i][1]);
            }
        }
    }
#pragma unroll
    for (int i = 0; i < 4; i++) {
        int oc = ty*4 + i;
        u64 bd = dup2(bc[oc]);
        float* p = &g_comp[(n*CCH + oc)*P + p0 + tx*4];
        *(u64*)p       = add2(acc[i][0], bd);
        *(u64*)(p + 2) = add2(acc[i][1], bd);
    }
}

// ---------------------------------------------------------------------------
// Kernel B: 3x3 conv encoder, packed f32x2 over oc-pairs.
// block = 64 threads: thread = (xg 0..7 -> 2 px, ty 0..7). Tile 8h x 16w.
// 25 oc as 13 float2 pairs (last padded). K split across grid (kh): 32 ch each.
// grid: (32 tiles, 4 n, 4 ocg * 2 kh) = 1024 blocks.
// ---------------------------------------------------------------------------
__global__ __launch_bounds__(64)
void k_encode(const float* __restrict__ We, const float* __restrict__ be) {
    __shared__ __align__(16) float tile[8*184];      // [c][10][18] stride 184
    __shared__ __align__(16) float2 wgt2[8*9*14];    // [c][tap][14 oc-pairs]
    const int bx = blockIdx.x;
    const int h0 = (bx >> 2) * 8;
    const int w0 = (bx & 3) * 16;
    const int n  = blockIdx.y;
    const int oc0 = (blockIdx.z & 3) * 25;
    const int kh  = blockIdx.z >> 2;
    const int cbase = kh * 32;
    const int xg = threadIdx.x & 7;
    const int ty = threadIdx.x >> 3;
    float* __restrict__ gout = kh ? g_m2 : g_m;

    u64 accA[13], accB[13];
#pragma unroll
    for (int q = 0; q < 13; q++) { accA[q] = 0ull; accB[q] = 0ull; }

    for (int cc0 = 0; cc0 < 32; cc0 += 8) {
        const int cs = cbase + cc0;
        __syncthreads();
        for (int idx = threadIdx.x; idx < 8*180; idx += 64) {
            int c = idx / 180, q = idx % 180;
            int yy = q / 18, xx = q % 18;
            int gy = h0 + yy - 1, gx = w0 + xx - 1;
            float v = 0.f;
            if (gy >= 0 && gy < H && gx >= 0 && gx < W)
                v = g_comp[(n*CCH + cs + c)*P + gy*W + gx];
            tile[c*184 + q] = v;
        }
        for (int idx = threadIdx.x; idx < 8*117; idx += 64) {
            int c = idx / 117, r = idx % 117;
            int tap = r / 13, qq = r % 13;
            float wa = We[((oc0 + 2*qq)*CCH + cs + c)*9 + tap];
            float wb = (2*qq + 1 < 25) ? We[((oc0 + 2*qq + 1)*CCH + cs + c)*9 + tap] : 0.f;
            wgt2[(c*9 + tap)*14 + qq] = make_float2(wa, wb);
        }
        __syncthreads();
#pragma unroll 1
        for (int c = 0; c < 8; c++) {
            const int base = c*184 + ty*18 + xg*2;
#pragma unroll
            for (int ky = 0; ky < 3; ky++) {
                float2 fa = *(const float2*)&tile[base + ky*18];
                float2 fb = *(const float2*)&tile[base + ky*18 + 2];
                u64 dv[4];
                dv[0] = dup2(fa.x); dv[1] = dup2(fa.y);
                dv[2] = dup2(fb.x); dv[3] = dup2(fb.y);
#pragma unroll
                for (int kx = 0; kx < 3; kx++) {
                    u64 v0 = dv[kx];        // px0 tap value
                    u64 v1 = dv[kx + 1];    // px1 tap value
                    const float2* wp = &wgt2[(c*9 + ky*3 + kx)*14];
#pragma unroll
                    for (int q2 = 0; q2 < 6; q2++) {
                        ulonglong2 ww = *(const ulonglong2*)(wp + q2*2);
                        accA[q2*2]   = fma2(v0, ww.x, accA[q2*2]);
                        accB[q2*2]   = fma2(v1, ww.x, accB[q2*2]);
                        accA[q2*2+1] = fma2(v0, ww.y, accA[q2*2+1]);
                        accB[q2*2+1] = fma2(v1, ww.y, accB[q2*2+1]);
                    }
                    u64 w12 = *(const u64*)(wp + 12);
                    accA[12] = fma2(v0, w12, accA[12]);
                    accB[12] = fma2(v1, w12, accB[12]);
                }
            }
        }
    }

    const int y = h0 + ty, xpx = w0 + xg*2;
#pragma unroll
    for (int q = 0; q < 13; q++) {
        float a0, a1, b0, b1;
        unpack2(accA[q], a0, a1);   // px0: oc 2q, 2q+1
        unpack2(accB[q], b0, b1);   // px1
        int oc = oc0 + 2*q;
        float bias0 = kh ? 0.f : be[oc];
        *(float2*)&gout[(n*ENC + oc)*P + y*W + xpx] = make_float2(a0 + bias0, b0 + bias0);
        if (2*q + 1 < 25) {
            float bias1 = kh ? 0.f : be[oc + 1];
            *(float2*)&gout[(n*ENC + oc + 1)*P + y*W + xpx] = make_float2(a1 + bias1, b1 + bias1);
        }
    }
}

// ---------------------------------------------------------------------------
// Kernel D: fused pixel-shuffle softmax + reassembly, packed f32x2 over the
// two horizontal subpixels. masks: 25 x {sub0,sub1} + 25 x {sub2,sub3} u64.
// Per tap: 1 LDS + 1 dup + 2 pFMA. grid (64 tiles, 4 n, 4 cgrp), 256 thr.
// ---------------------------------------------------------------------------
__global__ __launch_bounds__(256, 2)
void k_reassemble(const float* __restrict__ x, float* __restrict__ out) {
    __shared__ float ms[ENC*65];
    __shared__ float xs[16*168];
    const int t   = blockIdx.x;
    const int n   = blockIdx.y;
    const int c00 = blockIdx.z * 64;
    const int h0 = (t >> 3) * 8, w0 = (t & 7) * 8;
    const int cl = threadIdx.x & 3;
    const int p  = threadIdx.x >> 2;          // 0..63
    const int h  = p >> 3, w = p & 7;
    const int gh = h0 + h, gw = w0 + w;

    // stage encoder logits (sum of the two K-halves), coalesced
    for (int idx = threadIdx.x; idx < ENC*64; idx += 256) {
        int ch = idx >> 6, pp = idx & 63;
        int src = (n*ENC + ch)*P + (h0 + (pp>>3))*W + w0 + (pp&7);
        ms[ch*65 + pp] = g_m[src] + g_m2[src];
    }
    __syncthreads();

    // softmax over 25 taps: thread -> (pixel p, sub = cl)
    {
        float tv[25], mx = -1e30f;
#pragma unroll
        for (int k = 0; k < 25; k++) {
            tv[k] = ms[(k*4 + cl)*65 + p];
            mx = fmaxf(mx, tv[k]);
        }
        float s = 0.f;
#pragma unroll
        for (int k = 0; k < 25; k++) { tv[k] = __expf(tv[k] - mx); s += tv[k]; }
        float inv = 1.f / s;
#pragma unroll
        for (int k = 0; k < 25; k++) ms[(k*4 + cl)*65 + p] = tv[k]*inv;
    }
    __syncthreads();

    // packed mask registers: {sub0,sub1} and {sub2,sub3}
    u64 mk01[25], mk23[25];
#pragma unroll
    for (int k = 0; k < 25; k++) {
        mk01[k] = pack2(ms[(k*4 + 0)*65 + p], ms[(k*4 + 1)*65 + p]);
        mk23[k] = pack2(ms[(k*4 + 2)*65 + p], ms[(k*4 + 3)*65 + p]);
    }

    int sp = -1;
    if (threadIdx.x < 144) {
        int yy = threadIdx.x / 12, xx = threadIdx.x % 12;
        int gy = h0 + yy - 2, gx = w0 + xx - 2;
        if (gy >= 0 && gy < H && gx >= 0 && gx < W) sp = gy*W + gx;
    }
    const float* xb = x + (n*C + c00)*P;
    float* ob = out + (size_t)(n*C + c00)*HO*WO + (2*gh)*WO + 2*gw;

    for (int rr = 0; rr < 4; rr++) {
        __syncthreads();
        if (threadIdx.x < 144) {
            const float* xc = xb + rr*16*P;
#pragma unroll
            for (int c = 0; c < 16; c++)
                xs[c*168 + threadIdx.x] = (sp >= 0) ? xc[c*P + sp] : 0.f;
        }
        __syncthreads();
#pragma unroll
        for (int cc = 0; cc < 4; cc++) {
            int c = cl + cc*4;                 // conflict-free banking
            const float* xp = &xs[c*168 + h*12 + w];
            u64 a01 = 0ull, a23 = 0ull;
#pragma unroll
            for (int ky = 0; ky < 5; ky++)
#pragma unroll
                for (int kx = 0; kx < 5; kx++) {
                    u64 vd = dup2(xp[ky*12 + kx]);
                    int k = ky*5 + kx;
                    a01 = fma2(vd, mk01[k], a01);
                    a23 = fma2(vd, mk23[k], a23);
                }
            float* o = ob + (size_t)(rr*16 + c)*HO*WO;
            *(u64*)o        = a01;
            *(u64*)(o + WO) = a23;
        }
    }
}

// ---------------------------------------------------------------------------
extern "C" void kernel_launch(void* const* d_in, const int* in_sizes, int n_in,
                              void* d_out, int out_size) {
    const float* x  = (const float*)d_in[0];
    const float* Wc = (const float*)d_in[1];
    const float* bc = (const float*)d_in[2];
    const float* We = (const float*)d_in[3];
    const float* be = (const float*)d_in[4];
    float* out = (float*)d_out;

    k_transpose <<<64, 256>>>(Wc);
    k_compress  <<<dim3(128, NN), 128>>>(x, bc);
    k_encode    <<<dim3(32, NN, 8), 64>>>(We, be);
    k_reassemble<<<dim3(64, NN, 4), 256>>>(x, out);
}